// round 4
// baseline (speedup 1.0000x reference)
#include <cuda_runtime.h>
#include <math.h>

#define BB 64
#define PP 196
#define DD 2048
#define EE 512
#define HH 512
#define AA 512
#define VV 32000
#define SS 22
#define TT 20

static const size_t CAPS_OFF = (size_t)BB * TT * VV;
static const size_t LENS_OFF = CAPS_OFF + (size_t)BB * SS;
static const size_t ALPH_OFF = LENS_OFF + BB;
static const size_t SORT_OFF = ALPH_OFF + (size_t)BB * TT * PP;

// ---------------- device scratch (no allocations allowed) ----------------
__device__ int   g_sort[BB];
__device__ int   g_lens[BB];
__device__ int   g_caps[BB * SS];
__device__ float g_mean[BB * DD];
__device__ float g_h[BB * HH];
__device__ float g_c[BB * HH];
__device__ float g_att1[(size_t)BB * PP * AA];      // 25.7 MB
__device__ float g_att2p[4 * BB * AA];              // split-K partials
__device__ float g_alpha[BB * PP];
__device__ float g_gatep[2 * BB * DD];              // split-K partials (also c0 parts)
__device__ float g_X[BB * 3072];                    // [emb(512)|gate*awe(2048)|h(512)]
__device__ float g_WT[(size_t)3072 * 2048];         // [Wih|Whh]^T
__device__ float g_gp[(size_t)6 * BB * 2048];       // split-K partials (also h0 parts)
__device__ float g_Hall[(size_t)TT * BB * HH];

__device__ __forceinline__ float sigf(float x) { return 1.f / (1.f + expf(-x)); }

// ---------------- sort (stable, descending) + caps/lens/sort outputs -----
__global__ void k_sort(const int* __restrict__ cl,
                       const int* __restrict__ captions,
                       float* __restrict__ out)
{
    int tid = threadIdx.x;
    if (tid == 0) {
        int idx = 0;
        for (int v = SS; v >= 0; --v)
            for (int i = 0; i < BB; ++i)
                if (cl[i] == v) { g_sort[idx] = i; g_lens[idx] = v; ++idx; }
    }
    __syncthreads();
    for (int i = tid; i < BB * SS; i += blockDim.x) {
        int b = i / SS, s = i % SS;
        int cv = captions[s * BB + g_sort[b]];
        g_caps[i] = cv;
        out[CAPS_OFF + i] = (float)cv;
    }
    if (tid < BB) {
        out[LENS_OFF + tid] = (float)g_lens[tid];
        out[SORT_OFF + tid] = (float)g_sort[tid];
    }
}

// ---------------- build [Wih | Whh]^T -------------------------------------
__global__ void k_transpose(const float* __restrict__ Wih,
                            const float* __restrict__ Whh)
{
    __shared__ float tile[32][33];
    int k0 = blockIdx.x * 32, j0 = blockIdx.y * 32;
    int tx = threadIdx.x, ty = threadIdx.y;
    #pragma unroll
    for (int yy = 0; yy < 32; yy += 8) {
        int j = j0 + ty + yy, k = k0 + tx;
        tile[ty + yy][tx] = (k < 2560) ? Wih[(size_t)j * 2560 + k]
                                       : Whh[(size_t)j * 512 + (k - 2560)];
    }
    __syncthreads();
    #pragma unroll
    for (int yy = 0; yy < 32; yy += 8) {
        int k = k0 + ty + yy, j = j0 + tx;
        g_WT[(size_t)k * 2048 + j] = tile[tx][ty + yy];
    }
}

// ---------------- mean over pixels (gathered) -----------------------------
__global__ void k_mean(const float* __restrict__ features)
{
    int b = blockIdx.y;
    int d = blockIdx.x * 256 + threadIdx.x;
    const float* fb = features + (size_t)g_sort[b] * PP * DD + d;
    float s = 0.f;
    #pragma unroll 4
    for (int p = 0; p < PP; ++p) s += fb[(size_t)p * DD];
    g_mean[b * DD + d] = s * (1.f / 196.f);
}

// ---------------- M=64 split-K GEMM: part[ky] = A[64,kchunk]@B[kchunk,N] --
__global__ void __launch_bounds__(256)
gemm64(const float* __restrict__ A, int lda,
       const float* __restrict__ B, int ldb,
       float* __restrict__ Cp, int N, int kchunk)
{
    __shared__ float As[16][68];
    __shared__ float Bs[16][68];
    int tid = threadIdx.x;
    int n0 = blockIdx.x * 64;
    int k0 = blockIdx.y * kchunk;
    int ar = tid >> 2, ac = (tid & 3) * 4;
    int br = tid >> 4, bc = (tid & 15) * 4;
    const float* pA = A + (size_t)ar * lda + k0 + ac;
    const float* pB = B + (size_t)(k0 + br) * ldb + n0 + bc;
    int tx = tid & 15, ty = tid >> 4;
    float acc[4][4] = {};
    for (int kt = 0; kt < kchunk; kt += 16) {
        float4 a4 = *(const float4*)(pA + kt);
        float4 b4 = *(const float4*)(pB + (size_t)kt * ldb);
        __syncthreads();
        As[ac + 0][ar] = a4.x; As[ac + 1][ar] = a4.y;
        As[ac + 2][ar] = a4.z; As[ac + 3][ar] = a4.w;
        *(float4*)&Bs[br][bc] = b4;
        __syncthreads();
        #pragma unroll
        for (int kk = 0; kk < 16; ++kk) {
            float4 av = *(const float4*)&As[kk][ty * 4];
            float4 bv = *(const float4*)&Bs[kk][tx * 4];
            float am[4] = {av.x, av.y, av.z, av.w};
            float bn[4] = {bv.x, bv.y, bv.z, bv.w};
            #pragma unroll
            for (int i = 0; i < 4; ++i)
                #pragma unroll
                for (int j = 0; j < 4; ++j) acc[i][j] += am[i] * bn[j];
        }
    }
    float* C = Cp + (size_t)blockIdx.y * 64 * N;
    #pragma unroll
    for (int i = 0; i < 4; ++i) {
        int m = ty * 4 + i;
        #pragma unroll
        for (int j = 0; j < 4; ++j)
            C[(size_t)m * N + n0 + tx * 4 + j] = acc[i][j];
    }
}

// ---------------- 128x128 SGEMM. MODE0: att1 (row gather, +be).
//                  MODE1: preds (mask + scatter to out, +bout). ------------
template<int MODE>
__global__ void __launch_bounds__(256)
sgemm128(const float* __restrict__ A, int lda,
         const float* __restrict__ B, int ldb,
         const float* __restrict__ bias,
         float* __restrict__ C, int K)
{
    __shared__ float As[8][132];
    __shared__ float Bs[8][132];
    int tid = threadIdx.x;
    int m0 = blockIdx.y * 128, n0 = blockIdx.x * 128;
    int amr = tid >> 1, akc = (tid & 1) * 4;
    int arow = m0 + amr;
    if (MODE == 0) arow = g_sort[arow / PP] * PP + arow % PP;
    const float* pA = A + (size_t)arow * lda + akc;
    int brr = tid >> 5, bn4 = (tid & 31) * 4;
    const float* pB = B + (size_t)brr * ldb + n0 + bn4;
    int tx = tid & 15, ty = tid >> 4;
    float acc[8][8] = {};
    for (int kt = 0; kt < K; kt += 8) {
        float4 a4 = *(const float4*)(pA + kt);
        float4 b4 = *(const float4*)(pB + (size_t)kt * ldb);
        __syncthreads();
        As[akc + 0][amr] = a4.x; As[akc + 1][amr] = a4.y;
        As[akc + 2][amr] = a4.z; As[akc + 3][amr] = a4.w;
        *(float4*)&Bs[brr][bn4] = b4;
        __syncthreads();
        #pragma unroll
        for (int kk = 0; kk < 8; ++kk) {
            float4 a0 = *(const float4*)&As[kk][ty * 4];
            float4 a1 = *(const float4*)&As[kk][ty * 4 + 64];
            float4 b0 = *(const float4*)&Bs[kk][tx * 4];
            float4 b1 = *(const float4*)&Bs[kk][tx * 4 + 64];
            float am[8] = {a0.x, a0.y, a0.z, a0.w, a1.x, a1.y, a1.z, a1.w};
            float bn[8] = {b0.x, b0.y, b0.z, b0.w, b1.x, b1.y, b1.z, b1.w};
            #pragma unroll
            for (int i = 0; i < 8; ++i)
                #pragma unroll
                for (int j = 0; j < 8; ++j) acc[i][j] += am[i] * bn[j];
        }
    }
    #pragma unroll
    for (int i = 0; i < 8; ++i) {
        int m = m0 + ((i < 4) ? ty * 4 + i : 64 + ty * 4 + (i - 4));
        size_t orow;
        float msk = 1.f;
        if (MODE == 1) {
            int t = m >> 6, bb = m & 63;
            msk = (g_lens[bb] - 1 > t) ? 1.f : 0.f;
            orow = ((size_t)bb * TT + t) * VV;
        } else {
            orow = (size_t)m * AA;
        }
        #pragma unroll
        for (int j = 0; j < 8; ++j) {
            int n = n0 + ((j < 4) ? tx * 4 + j : 64 + tx * 4 + (j - 4));
            C[orow + n] = (acc[i][j] + bias[n]) * msk;
        }
    }
}

// ---------------- h0/c0 epilogue ------------------------------------------
__global__ void k_initstate(const float* __restrict__ bh0,
                            const float* __restrict__ bc0)
{
    int b = blockIdx.y;
    int j = blockIdx.x * 256 + threadIdx.x;
    float h = bh0[j], c = bc0[j];
    #pragma unroll
    for (int ks = 0; ks < 4; ++ks) {
        h += g_gp[(size_t)ks * BB * 512 + b * 512 + j];
        c += g_gatep[(size_t)ks * BB * 512 + b * 512 + j];
    }
    g_h[b * HH + j] = h;
    g_c[b * HH + j] = c;
}

// ---------------- attention scores + softmax (fuses att2 split-K reduce) --
__global__ void __launch_bounds__(256)
k_softmax(const float* __restrict__ wf, const float* __restrict__ bf,
          const float* __restrict__ bd, int t, float* __restrict__ out)
{
    __shared__ float att2s[512];
    __shared__ float scr[PP];
    __shared__ float red[256];
    int b = blockIdx.x, tid = threadIdx.x;
    for (int a = tid; a < 512; a += 256) {
        float v = bd[a];
        #pragma unroll
        for (int ks = 0; ks < 4; ++ks) v += g_att2p[ks * BB * AA + b * AA + a];
        att2s[a] = v;
    }
    __syncthreads();
    int w = tid >> 5, l = tid & 31;
    for (int p = w; p < PP; p += 8) {
        const float4* A1 = (const float4*)(g_att1 + ((size_t)b * PP + p) * AA);
        const float4* W4 = (const float4*)wf;
        float v = 0.f;
        #pragma unroll
        for (int j = 0; j < 4; ++j) {
            int q = j * 32 + l;
            float4 x = A1[q], y = W4[q];
            int a = q * 4;
            v += fmaxf(x.x + att2s[a + 0], 0.f) * y.x;
            v += fmaxf(x.y + att2s[a + 1], 0.f) * y.y;
            v += fmaxf(x.z + att2s[a + 2], 0.f) * y.z;
            v += fmaxf(x.w + att2s[a + 3], 0.f) * y.w;
        }
        #pragma unroll
        for (int o = 16; o; o >>= 1) v += __shfl_down_sync(0xffffffffu, v, o);
        if (l == 0) scr[p] = v + bf[0];
    }
    __syncthreads();
    red[tid] = (tid < PP) ? scr[tid] : -1e30f;
    __syncthreads();
    for (int s = 128; s; s >>= 1) {
        if (tid < s) red[tid] = fmaxf(red[tid], red[tid + s]);
        __syncthreads();
    }
    float mx = red[0];
    __syncthreads();
    float e = (tid < PP) ? expf(scr[tid] - mx) : 0.f;
    red[tid] = e;
    __syncthreads();
    for (int s = 128; s; s >>= 1) {
        if (tid < s) red[tid] += red[tid + s];
        __syncthreads();
    }
    float inv = 1.f / red[0];
    if (tid < PP) {
        float al = e * inv;
        g_alpha[b * PP + tid] = al;
        float msk = (g_lens[b] - 1 > t) ? 1.f : 0.f;
        out[ALPH_OFF + ((size_t)b * TT + t) * PP + tid] = al * msk;
    }
}

// ---------------- awe + gate (fuses gatepre split-K reduce) + X assembly --
__global__ void __launch_bounds__(256)
k_xassemble(const float* __restrict__ features, const float* __restrict__ embW,
            const float* __restrict__ bbeta, int t)
{
    __shared__ float al[PP];
    int b = blockIdx.y, tid = threadIdx.x;
    int d = blockIdx.x * 256 + tid;
    if (tid < PP) al[tid] = g_alpha[b * PP + tid];
    __syncthreads();
    const float* fb = features + (size_t)g_sort[b] * PP * DD + d;
    float awe = 0.f;
    #pragma unroll 4
    for (int p = 0; p < PP; ++p) awe += fb[(size_t)p * DD] * al[p];
    float gp = g_gatep[b * DD + d] + g_gatep[BB * DD + b * DD + d] + bbeta[d];
    g_X[b * 3072 + 512 + d] = awe * sigf(gp);
    if (blockIdx.x == 0) {
        int cap = g_caps[b * SS + t];
        g_X[b * 3072 + tid]        = embW[(size_t)cap * EE + tid];
        g_X[b * 3072 + tid + 256]  = embW[(size_t)cap * EE + tid + 256];
        g_X[b * 3072 + 2560 + tid] = g_h[b * HH + tid];
        g_X[b * 3072 + 2816 + tid] = g_h[b * HH + tid + 256];
    }
}

// ---------------- LSTM pointwise (fuses gates split-K reduce) -------------
__global__ void k_lstm(const float* __restrict__ bih,
                       const float* __restrict__ bhh, int t)
{
    int b = blockIdx.y;
    int j = blockIdx.x * 256 + threadIdx.x;
    float ii = bih[j]        + bhh[j];
    float ff = bih[j + 512]  + bhh[j + 512];
    float gg = bih[j + 1024] + bhh[j + 1024];
    float oo = bih[j + 1536] + bhh[j + 1536];
    #pragma unroll
    for (int ks = 0; ks < 6; ++ks) {
        const float* p = g_gp + (size_t)ks * BB * 2048 + b * 2048;
        ii += p[j]; ff += p[j + 512]; gg += p[j + 1024]; oo += p[j + 1536];
    }
    float c = sigf(ff) * g_c[b * HH + j] + sigf(ii) * tanhf(gg);
    float h = sigf(oo) * tanhf(c);
    g_c[b * HH + j] = c;
    g_h[b * HH + j] = h;
    g_Hall[(size_t)t * BB * HH + b * HH + j] = h;
}

// ---------------- launch ---------------------------------------------------
extern "C" void kernel_launch(void* const* d_in, const int* in_sizes, int n_in,
                              void* d_out, int out_size)
{
    const float* features = (const float*)d_in[0];
    const int*   captions = (const int*)d_in[1];
    const int*   caplen   = (const int*)d_in[2];
    const float* embW  = (const float*)d_in[3];
    const float* We    = (const float*)d_in[4];
    const float* be    = (const float*)d_in[5];
    const float* Wd    = (const float*)d_in[6];
    const float* bd    = (const float*)d_in[7];
    const float* wf    = (const float*)d_in[8];
    const float* bf    = (const float*)d_in[9];
    const float* Wih   = (const float*)d_in[10];
    const float* Whh   = (const float*)d_in[11];
    const float* bih   = (const float*)d_in[12];
    const float* bhh   = (const float*)d_in[13];
    const float* Wh0   = (const float*)d_in[14];
    const float* bh0   = (const float*)d_in[15];
    const float* Wc0   = (const float*)d_in[16];
    const float* bc0   = (const float*)d_in[17];
    const float* Wbeta = (const float*)d_in[18];
    const float* bbeta = (const float*)d_in[19];
    const float* Wout  = (const float*)d_in[20];
    const float* bout  = (const float*)d_in[21];
    float* out = (float*)d_out;

    float *p_mean, *p_h, *p_X, *p_WT, *p_gp, *p_att2p, *p_gatep, *p_Hall, *p_att1;
    cudaGetSymbolAddress((void**)&p_mean,  g_mean);
    cudaGetSymbolAddress((void**)&p_h,     g_h);
    cudaGetSymbolAddress((void**)&p_X,     g_X);
    cudaGetSymbolAddress((void**)&p_WT,    g_WT);
    cudaGetSymbolAddress((void**)&p_gp,    g_gp);
    cudaGetSymbolAddress((void**)&p_att2p, g_att2p);
    cudaGetSymbolAddress((void**)&p_gatep, g_gatep);
    cudaGetSymbolAddress((void**)&p_Hall,  g_Hall);
    cudaGetSymbolAddress((void**)&p_att1,  g_att1);

    k_sort<<<1, 256>>>(caplen, captions, out);
    k_transpose<<<dim3(96, 64), dim3(32, 8)>>>(Wih, Whh);
    k_mean<<<dim3(8, 64), 256>>>(features);

    // h0/c0: split-K 4, K=2048
    gemm64<<<dim3(8, 4), 256>>>(p_mean, 2048, Wh0, 512, p_gp,    512, 512);
    gemm64<<<dim3(8, 4), 256>>>(p_mean, 2048, Wc0, 512, p_gatep, 512, 512);
    k_initstate<<<dim3(2, 64), 256>>>(bh0, bc0);

    // att1 = gather(enc) @ We + be
    sgemm128<0><<<dim3(4, 98), 256>>>(features, 2048, We, 512, be, p_att1, 2048);

    for (int t = 0; t < TT; ++t) {
        gemm64<<<dim3(8, 4),  256>>>(p_h, 512,  Wd,    512,  p_att2p, 512,  128);
        gemm64<<<dim3(32, 2), 256>>>(p_h, 512,  Wbeta, 2048, p_gatep, 2048, 256);
        k_softmax<<<64, 256>>>(wf, bf, bd, t, out);
        k_xassemble<<<dim3(8, 64), 256>>>(features, embW, bbeta, t);
        gemm64<<<dim3(32, 6), 256>>>(p_X, 3072, p_WT,  2048, p_gp,    2048, 512);
        k_lstm<<<dim3(2, 64), 256>>>(bih, bhh, t);
    }

    // predictions = Hall @ Wout + bout, masked + scattered to [b][t][v]
    sgemm128<1><<<dim3(250, 10), 256>>>(p_Hall, 512, Wout, 32000, bout, out, 512);
}

// round 5
// speedup vs baseline: 1.8152x; 1.8152x over previous
#include <cuda_runtime.h>
#include <math.h>

#define BB 64
#define PP 196
#define DD 2048
#define EE 512
#define HH 512
#define AA 512
#define VV 32000
#define SS 22
#define TT 20

static const size_t CAPS_OFF = (size_t)BB * TT * VV;
static const size_t LENS_OFF = CAPS_OFF + (size_t)BB * SS;
static const size_t ALPH_OFF = LENS_OFF + BB;
static const size_t SORT_OFF = ALPH_OFF + (size_t)BB * TT * PP;

// ---------------- device scratch (no allocations allowed) ----------------
__device__ int   g_sort[BB];
__device__ int   g_lens[BB];
__device__ int   g_caps[BB * SS];
__device__ float g_mean[BB * DD];
__device__ float g_h[BB * HH];
__device__ float g_c[BB * HH];
__device__ float g_att1[(size_t)BB * PP * AA];      // 25.7 MB
__device__ float g_att2p[4 * BB * AA];              // split-K partials
__device__ float g_alpha[BB * PP];
__device__ float g_gatep[2 * BB * DD];              // split-K partials (also c0 parts)
__device__ float g_X[BB * 3072];                    // [emb(512)|gate*awe(2048)|h(512)]
__device__ float g_WT[(size_t)3072 * 2048];         // [Wih|Whh]^T
__device__ float g_gp[(size_t)6 * BB * 2048];       // split-K partials (also h0 parts)
__device__ float g_Hall[(size_t)TT * BB * HH];

__device__ __forceinline__ float sigf(float x) { return 1.f / (1.f + expf(-x)); }

// ---------------- tf32 mma primitives -------------------------------------
__device__ __forceinline__ unsigned f2tf(float v) {
    unsigned r; asm("cvt.rna.tf32.f32 %0, %1;" : "=r"(r) : "f"(v)); return r;
}
__device__ __forceinline__ void mma8(float* d, const unsigned* a, const unsigned* b) {
    asm volatile("mma.sync.aligned.m16n8k8.row.col.f32.tf32.tf32.f32 "
                 "{%0,%1,%2,%3}, {%4,%5,%6,%7}, {%8,%9}, {%0,%1,%2,%3};"
                 : "+f"(d[0]), "+f"(d[1]), "+f"(d[2]), "+f"(d[3])
                 : "r"(a[0]), "r"(a[1]), "r"(a[2]), "r"(a[3]),
                   "r"(b[0]), "r"(b[1]));
}
__device__ __forceinline__ void cp16(unsigned dst, const float* src) {
    asm volatile("cp.async.cg.shared.global [%0], [%1], 16;" :: "r"(dst), "l"(src));
}

#define AS128 (128 * 36)
#define AS64  (64 * 36)
#define BS32  (32 * 132)
#define SM128B ((2 * AS128 + 2 * BS32) * 4)
#define SM64B  ((2 * AS64  + 2 * BS32) * 4)

// ---------------- sort (stable, descending) + caps/lens/sort outputs -----
__global__ void k_sort(const int* __restrict__ cl,
                       const int* __restrict__ captions,
                       float* __restrict__ out)
{
    int tid = threadIdx.x;
    if (tid == 0) {
        int idx = 0;
        for (int v = SS; v >= 0; --v)
            for (int i = 0; i < BB; ++i)
                if (cl[i] == v) { g_sort[idx] = i; g_lens[idx] = v; ++idx; }
    }
    __syncthreads();
    for (int i = tid; i < BB * SS; i += blockDim.x) {
        int b = i / SS, s = i % SS;
        int cv = captions[s * BB + g_sort[b]];
        g_caps[i] = cv;
        out[CAPS_OFF + i] = (float)cv;
    }
    if (tid < BB) {
        out[LENS_OFF + tid] = (float)g_lens[tid];
        out[SORT_OFF + tid] = (float)g_sort[tid];
    }
}

// ---------------- build [Wih | Whh]^T -------------------------------------
__global__ void k_transpose(const float* __restrict__ Wih,
                            const float* __restrict__ Whh)
{
    __shared__ float tile[32][33];
    int k0 = blockIdx.x * 32, j0 = blockIdx.y * 32;
    int tx = threadIdx.x, ty = threadIdx.y;
    #pragma unroll
    for (int yy = 0; yy < 32; yy += 8) {
        int j = j0 + ty + yy, k = k0 + tx;
        tile[ty + yy][tx] = (k < 2560) ? Wih[(size_t)j * 2560 + k]
                                       : Whh[(size_t)j * 512 + (k - 2560)];
    }
    __syncthreads();
    #pragma unroll
    for (int yy = 0; yy < 32; yy += 8) {
        int k = k0 + ty + yy, j = j0 + tx;
        g_WT[(size_t)k * 2048 + j] = tile[tx][ty + yy];
    }
}

// ---------------- mean over pixels (gathered) -----------------------------
__global__ void k_mean(const float* __restrict__ features)
{
    int b = blockIdx.y;
    int d = blockIdx.x * 256 + threadIdx.x;
    const float* fb = features + (size_t)g_sort[b] * PP * DD + d;
    float s = 0.f;
    #pragma unroll 4
    for (int p = 0; p < PP; ++p) s += fb[(size_t)p * DD];
    g_mean[b * DD + d] = s * (1.f / 196.f);
}

// ---------------- tf32 tensor-core GEMM, 128x128 tile ---------------------
// MODE0: att1 (row gather via g_sort, +bias, C ld = 512)
// MODE1: preds (mask by g_lens, +bias, scatter rows to out[b][t][*])
template<int MODE>
__global__ void __launch_bounds__(256)
mma128(const float* __restrict__ A, int lda,
       const float* __restrict__ B, int ldb,
       const float* __restrict__ bias,
       float* __restrict__ C, int K)
{
    extern __shared__ float sm[];
    float* smA = sm;                 // 2 * AS128 floats
    float* smB = sm + 2 * AS128;     // 2 * BS32 floats
    const int tid = threadIdx.x;
    const int n0 = blockIdx.x * 128, m0 = blockIdx.y * 128;

    // global->smem mapping
    const int seg  = tid & 7,  rb  = tid >> 3;    // A: 8 col-segs x 32 row groups
    const int cseg = tid & 31, rbb = tid >> 5;    // B: 32 col-segs x 8 row groups
    const float* ap[4];
    #pragma unroll
    for (int i = 0; i < 4; ++i) {
        int mrow = m0 + rb + 32 * i;
        if (MODE == 0) mrow = g_sort[mrow / PP] * PP + mrow % PP;
        ap[i] = A + (size_t)mrow * lda + seg * 4;
    }
    const float* bp[4];
    #pragma unroll
    for (int i = 0; i < 4; ++i)
        bp[i] = B + (size_t)(rbb + 8 * i) * ldb + n0 + cseg * 4;

    unsigned sA = (unsigned)__cvta_generic_to_shared(smA);
    unsigned sB = (unsigned)__cvta_generic_to_shared(smB);
    unsigned dA[4], dB[4];
    #pragma unroll
    for (int i = 0; i < 4; ++i) {
        dA[i] = sA + ((rb + 32 * i) * 36 + seg * 4) * 4;
        dB[i] = sB + ((rbb + 8 * i) * 132 + cseg * 4) * 4;
    }
    const unsigned ABYT = AS128 * 4, BBYT = BS32 * 4;

    const int lane = tid & 31, wid = tid >> 5;
    const int g = lane >> 2, tg = lane & 3;
    const int wm = (wid >> 2) * 64, wn = (wid & 3) * 32;
    float acc[4][4][4];
    #pragma unroll
    for (int a = 0; a < 4; ++a)
        #pragma unroll
        for (int b = 0; b < 4; ++b)
            #pragma unroll
            for (int c = 0; c < 4; ++c) acc[a][b][c] = 0.f;

    const int KC = K >> 5;
    #pragma unroll
    for (int i = 0; i < 4; ++i) cp16(dA[i], ap[i]);
    #pragma unroll
    for (int i = 0; i < 4; ++i) cp16(dB[i], bp[i]);
    asm volatile("cp.async.commit_group;");

    for (int kc = 0; kc < KC; ++kc) {
        int cur = kc & 1, nxt = cur ^ 1;
        if (kc + 1 < KC) {
            int k0 = (kc + 1) * 32;
            #pragma unroll
            for (int i = 0; i < 4; ++i) cp16(dA[i] + nxt * ABYT, ap[i] + k0);
            #pragma unroll
            for (int i = 0; i < 4; ++i) cp16(dB[i] + nxt * BBYT, bp[i] + (size_t)k0 * ldb);
            asm volatile("cp.async.commit_group;");
            asm volatile("cp.async.wait_group 1;");
        } else {
            asm volatile("cp.async.wait_group 0;");
        }
        __syncthreads();
        const float* a_s = smA + cur * AS128;
        const float* b_s = smB + cur * BS32;
        #pragma unroll
        for (int ks = 0; ks < 4; ++ks) {
            const int kb = ks * 8;
            unsigned af[4][4], bf[4][2];
            #pragma unroll
            for (int mt = 0; mt < 4; ++mt) {
                int r = wm + mt * 16 + g;
                af[mt][0] = f2tf(a_s[r * 36 + kb + tg]);
                af[mt][1] = f2tf(a_s[(r + 8) * 36 + kb + tg]);
                af[mt][2] = f2tf(a_s[r * 36 + kb + tg + 4]);
                af[mt][3] = f2tf(a_s[(r + 8) * 36 + kb + tg + 4]);
            }
            #pragma unroll
            for (int nt = 0; nt < 4; ++nt) {
                int cN = wn + nt * 8 + g;
                bf[nt][0] = f2tf(b_s[(kb + tg) * 132 + cN]);
                bf[nt][1] = f2tf(b_s[(kb + tg + 4) * 132 + cN]);
            }
            #pragma unroll
            for (int mt = 0; mt < 4; ++mt)
                #pragma unroll
                for (int nt = 0; nt < 4; ++nt)
                    mma8(acc[mt][nt], af[mt], bf[nt]);
        }
        __syncthreads();
    }

    #pragma unroll
    for (int mt = 0; mt < 4; ++mt) {
        #pragma unroll
        for (int hf = 0; hf < 2; ++hf) {
            int row = m0 + wm + mt * 16 + g + hf * 8;
            size_t orow; float msk = 1.f;
            if (MODE == 1) {
                int t = row >> 6, b = row & 63;
                msk = (g_lens[b] - 1 > t) ? 1.f : 0.f;
                orow = ((size_t)b * TT + t) * VV;
            } else {
                orow = (size_t)row * AA;
            }
            #pragma unroll
            for (int nt = 0; nt < 4; ++nt) {
                #pragma unroll
                for (int j = 0; j < 2; ++j) {
                    int col = n0 + wn + nt * 8 + tg * 2 + j;
                    float v = acc[mt][nt][hf * 2 + j] + bias[col];
                    C[orow + col] = (MODE == 1) ? v * msk : v;
                }
            }
        }
    }
}

// ---------------- tf32 tensor-core GEMM, 64xN, split-K partials -----------
// Writes Cp + blockIdx.y*64*N + m*N + n  (same layout the fused reducers expect)
__global__ void __launch_bounds__(128)
mma64(const float* __restrict__ A, int lda,
      const float* __restrict__ B, int ldb,
      float* __restrict__ Cp, int N, int kchunk)
{
    extern __shared__ float sm[];
    float* smA = sm;                // 2 * AS64
    float* smB = sm + 2 * AS64;     // 2 * BS32
    const int tid = threadIdx.x;
    const int n0 = blockIdx.x * 128;
    const int kbase = blockIdx.y * kchunk;

    const int seg  = tid & 7,  rb  = tid >> 3;    // rb 0..15
    const int cseg = tid & 31, rbb = tid >> 5;    // rbb 0..3
    const float* ap[4];
    #pragma unroll
    for (int i = 0; i < 4; ++i)
        ap[i] = A + (size_t)(rb + 16 * i) * lda + kbase + seg * 4;
    const float* bp[8];
    #pragma unroll
    for (int i = 0; i < 8; ++i)
        bp[i] = B + (size_t)(kbase + rbb + 4 * i) * ldb + n0 + cseg * 4;

    unsigned sA = (unsigned)__cvta_generic_to_shared(smA);
    unsigned sB = (unsigned)__cvta_generic_to_shared(smB);
    unsigned dA[4], dB[8];
    #pragma unroll
    for (int i = 0; i < 4; ++i) dA[i] = sA + ((rb + 16 * i) * 36 + seg * 4) * 4;
    #pragma unroll
    for (int i = 0; i < 8; ++i) dB[i] = sB + ((rbb + 4 * i) * 132 + cseg * 4) * 4;
    const unsigned ABYT = AS64 * 4, BBYT = BS32 * 4;

    const int lane = tid & 31, wid = tid >> 5;
    const int g = lane >> 2, tg = lane & 3;
    const int wn = wid * 32;
    float acc[4][4][4];
    #pragma unroll
    for (int a = 0; a < 4; ++a)
        #pragma unroll
        for (int b = 0; b < 4; ++b)
            #pragma unroll
            for (int c = 0; c < 4; ++c) acc[a][b][c] = 0.f;

    const int KC = kchunk >> 5;
    #pragma unroll
    for (int i = 0; i < 4; ++i) cp16(dA[i], ap[i]);
    #pragma unroll
    for (int i = 0; i < 8; ++i) cp16(dB[i], bp[i]);
    asm volatile("cp.async.commit_group;");

    for (int kc = 0; kc < KC; ++kc) {
        int cur = kc & 1, nxt = cur ^ 1;
        if (kc + 1 < KC) {
            int k0 = (kc + 1) * 32;
            #pragma unroll
            for (int i = 0; i < 4; ++i) cp16(dA[i] + nxt * ABYT, ap[i] + k0);
            #pragma unroll
            for (int i = 0; i < 8; ++i) cp16(dB[i] + nxt * BBYT, bp[i] + (size_t)k0 * ldb);
            asm volatile("cp.async.commit_group;");
            asm volatile("cp.async.wait_group 1;");
        } else {
            asm volatile("cp.async.wait_group 0;");
        }
        __syncthreads();
        const float* a_s = smA + cur * AS64;
        const float* b_s = smB + cur * BS32;
        #pragma unroll
        for (int ks = 0; ks < 4; ++ks) {
            const int kb = ks * 8;
            unsigned af[4][4], bf[4][2];
            #pragma unroll
            for (int mt = 0; mt < 4; ++mt) {
                int r = mt * 16 + g;
                af[mt][0] = f2tf(a_s[r * 36 + kb + tg]);
                af[mt][1] = f2tf(a_s[(r + 8) * 36 + kb + tg]);
                af[mt][2] = f2tf(a_s[r * 36 + kb + tg + 4]);
                af[mt][3] = f2tf(a_s[(r + 8) * 36 + kb + tg + 4]);
            }
            #pragma unroll
            for (int nt = 0; nt < 4; ++nt) {
                int cN = wn + nt * 8 + g;
                bf[nt][0] = f2tf(b_s[(kb + tg) * 132 + cN]);
                bf[nt][1] = f2tf(b_s[(kb + tg + 4) * 132 + cN]);
            }
            #pragma unroll
            for (int mt = 0; mt < 4; ++mt)
                #pragma unroll
                for (int nt = 0; nt < 4; ++nt)
                    mma8(acc[mt][nt], af[mt], bf[nt]);
        }
        __syncthreads();
    }

    float* Cb = Cp + (size_t)blockIdx.y * 64 * N;
    #pragma unroll
    for (int mt = 0; mt < 4; ++mt) {
        #pragma unroll
        for (int hf = 0; hf < 2; ++hf) {
            int row = mt * 16 + g + hf * 8;
            #pragma unroll
            for (int nt = 0; nt < 4; ++nt) {
                #pragma unroll
                for (int j = 0; j < 2; ++j) {
                    int col = n0 + wn + nt * 8 + tg * 2 + j;
                    Cb[(size_t)row * N + col] = acc[mt][nt][hf * 2 + j];
                }
            }
        }
    }
}

// ---------------- h0/c0 epilogue ------------------------------------------
__global__ void k_initstate(const float* __restrict__ bh0,
                            const float* __restrict__ bc0)
{
    int b = blockIdx.y;
    int j = blockIdx.x * 256 + threadIdx.x;
    float h = bh0[j], c = bc0[j];
    #pragma unroll
    for (int ks = 0; ks < 4; ++ks) {
        h += g_gp[(size_t)ks * BB * 512 + b * 512 + j];
        c += g_gatep[(size_t)ks * BB * 512 + b * 512 + j];
    }
    g_h[b * HH + j] = h;
    g_c[b * HH + j] = c;
}

// ---------------- attention scores + softmax (fuses att2 split-K reduce) --
__global__ void __launch_bounds__(256)
k_softmax(const float* __restrict__ wf, const float* __restrict__ bf,
          const float* __restrict__ bd, int t, float* __restrict__ out)
{
    __shared__ float att2s[512];
    __shared__ float scr[PP];
    __shared__ float red[256];
    int b = blockIdx.x, tid = threadIdx.x;
    for (int a = tid; a < 512; a += 256) {
        float v = bd[a];
        #pragma unroll
        for (int ks = 0; ks < 4; ++ks) v += g_att2p[ks * BB * AA + b * AA + a];
        att2s[a] = v;
    }
    __syncthreads();
    int w = tid >> 5, l = tid & 31;
    for (int p = w; p < PP; p += 8) {
        const float4* A1 = (const float4*)(g_att1 + ((size_t)b * PP + p) * AA);
        const float4* W4 = (const float4*)wf;
        float v = 0.f;
        #pragma unroll
        for (int j = 0; j < 4; ++j) {
            int q = j * 32 + l;
            float4 x = A1[q], y = W4[q];
            int a = q * 4;
            v += fmaxf(x.x + att2s[a + 0], 0.f) * y.x;
            v += fmaxf(x.y + att2s[a + 1], 0.f) * y.y;
            v += fmaxf(x.z + att2s[a + 2], 0.f) * y.z;
            v += fmaxf(x.w + att2s[a + 3], 0.f) * y.w;
        }
        #pragma unroll
        for (int o = 16; o; o >>= 1) v += __shfl_down_sync(0xffffffffu, v, o);
        if (l == 0) scr[p] = v + bf[0];
    }
    __syncthreads();
    red[tid] = (tid < PP) ? scr[tid] : -1e30f;
    __syncthreads();
    for (int s = 128; s; s >>= 1) {
        if (tid < s) red[tid] = fmaxf(red[tid], red[tid + s]);
        __syncthreads();
    }
    float mx = red[0];
    __syncthreads();
    float e = (tid < PP) ? expf(scr[tid] - mx) : 0.f;
    red[tid] = e;
    __syncthreads();
    for (int s = 128; s; s >>= 1) {
        if (tid < s) red[tid] += red[tid + s];
        __syncthreads();
    }
    float inv = 1.f / red[0];
    if (tid < PP) {
        float al = e * inv;
        g_alpha[b * PP + tid] = al;
        float msk = (g_lens[b] - 1 > t) ? 1.f : 0.f;
        out[ALPH_OFF + ((size_t)b * TT + t) * PP + tid] = al * msk;
    }
}

// ---------------- awe + gate (fuses gatepre split-K reduce) + X assembly --
__global__ void __launch_bounds__(256)
k_xassemble(const float* __restrict__ features, const float* __restrict__ embW,
            const float* __restrict__ bbeta, int t)
{
    __shared__ float al[PP];
    int b = blockIdx.y, tid = threadIdx.x;
    int d = blockIdx.x * 256 + tid;
    if (tid < PP) al[tid] = g_alpha[b * PP + tid];
    __syncthreads();
    const float* fb = features + (size_t)g_sort[b] * PP * DD + d;
    float awe = 0.f;
    #pragma unroll 4
    for (int p = 0; p < PP; ++p) awe += fb[(size_t)p * DD] * al[p];
    float gp = g_gatep[b * DD + d] + g_gatep[BB * DD + b * DD + d] + bbeta[d];
    g_X[b * 3072 + 512 + d] = awe * sigf(gp);
    if (blockIdx.x == 0) {
        int cap = g_caps[b * SS + t];
        g_X[b * 3072 + tid]        = embW[(size_t)cap * EE + tid];
        g_X[b * 3072 + tid + 256]  = embW[(size_t)cap * EE + tid + 256];
        g_X[b * 3072 + 2560 + tid] = g_h[b * HH + tid];
        g_X[b * 3072 + 2816 + tid] = g_h[b * HH + tid + 256];
    }
}

// ---------------- LSTM pointwise (fuses gates split-K reduce) -------------
__global__ void k_lstm(const float* __restrict__ bih,
                       const float* __restrict__ bhh, int t)
{
    int b = blockIdx.y;
    int j = blockIdx.x * 256 + threadIdx.x;
    float ii = bih[j]        + bhh[j];
    float ff = bih[j + 512]  + bhh[j + 512];
    float gg = bih[j + 1024] + bhh[j + 1024];
    float oo = bih[j + 1536] + bhh[j + 1536];
    #pragma unroll
    for (int ks = 0; ks < 6; ++ks) {
        const float* p = g_gp + (size_t)ks * BB * 2048 + b * 2048;
        ii += p[j]; ff += p[j + 512]; gg += p[j + 1024]; oo += p[j + 1536];
    }
    float c = sigf(ff) * g_c[b * HH + j] + sigf(ii) * tanhf(gg);
    float h = sigf(oo) * tanhf(c);
    g_c[b * HH + j] = c;
    g_h[b * HH + j] = h;
    g_Hall[(size_t)t * BB * HH + b * HH + j] = h;
}

// ---------------- launch ---------------------------------------------------
extern "C" void kernel_launch(void* const* d_in, const int* in_sizes, int n_in,
                              void* d_out, int out_size)
{
    const float* features = (const float*)d_in[0];
    const int*   captions = (const int*)d_in[1];
    const int*   caplen   = (const int*)d_in[2];
    const float* embW  = (const float*)d_in[3];
    const float* We    = (const float*)d_in[4];
    const float* be    = (const float*)d_in[5];
    const float* Wd    = (const float*)d_in[6];
    const float* bd    = (const float*)d_in[7];
    const float* wf    = (const float*)d_in[8];
    const float* bf    = (const float*)d_in[9];
    const float* Wih   = (const float*)d_in[10];
    const float* Whh   = (const float*)d_in[11];
    const float* bih   = (const float*)d_in[12];
    const float* bhh   = (const float*)d_in[13];
    const float* Wh0   = (const float*)d_in[14];
    const float* bh0   = (const float*)d_in[15];
    const float* Wc0   = (const float*)d_in[16];
    const float* bc0   = (const float*)d_in[17];
    const float* Wbeta = (const float*)d_in[18];
    const float* bbeta = (const float*)d_in[19];
    const float* Wout  = (const float*)d_in[20];
    const float* bout  = (const float*)d_in[21];
    float* out = (float*)d_out;

    float *p_mean, *p_h, *p_X, *p_WT, *p_gp, *p_att2p, *p_gatep, *p_Hall, *p_att1;
    cudaGetSymbolAddress((void**)&p_mean,  g_mean);
    cudaGetSymbolAddress((void**)&p_h,     g_h);
    cudaGetSymbolAddress((void**)&p_X,     g_X);
    cudaGetSymbolAddress((void**)&p_WT,    g_WT);
    cudaGetSymbolAddress((void**)&p_gp,    g_gp);
    cudaGetSymbolAddress((void**)&p_att2p, g_att2p);
    cudaGetSymbolAddress((void**)&p_gatep, g_gatep);
    cudaGetSymbolAddress((void**)&p_Hall,  g_Hall);
    cudaGetSymbolAddress((void**)&p_att1,  g_att1);

    cudaFuncSetAttribute(mma128<0>, cudaFuncAttributeMaxDynamicSharedMemorySize, SM128B);
    cudaFuncSetAttribute(mma128<1>, cudaFuncAttributeMaxDynamicSharedMemorySize, SM128B);
    cudaFuncSetAttribute(mma64,     cudaFuncAttributeMaxDynamicSharedMemorySize, SM64B);

    k_sort<<<1, 256>>>(caplen, captions, out);
    k_transpose<<<dim3(96, 64), dim3(32, 8)>>>(Wih, Whh);
    k_mean<<<dim3(8, 64), 256>>>(features);

    // h0/c0: K=2048 split 4
    mma64<<<dim3(4, 4), 128, SM64B>>>(p_mean, 2048, Wh0, 512, p_gp,    512, 512);
    mma64<<<dim3(4, 4), 128, SM64B>>>(p_mean, 2048, Wc0, 512, p_gatep, 512, 512);
    k_initstate<<<dim3(2, 64), 256>>>(bh0, bc0);

    // att1 = gather(enc) @ We + be  (tf32 tensor cores)
    mma128<0><<<dim3(4, 98), 256, SM128B>>>(features, 2048, We, 512, be, p_att1, 2048);

    for (int t = 0; t < TT; ++t) {
        mma64<<<dim3(4, 4),  128, SM64B>>>(p_h, 512,  Wd,    512,  p_att2p, 512,  128);
        mma64<<<dim3(16, 2), 128, SM64B>>>(p_h, 512,  Wbeta, 2048, p_gatep, 2048, 256);
        k_softmax<<<64, 256>>>(wf, bf, bd, t, out);
        k_xassemble<<<dim3(8, 64), 256>>>(features, embW, bbeta, t);
        mma64<<<dim3(16, 6), 128, SM64B>>>(p_X, 3072, p_WT, 2048, p_gp, 2048, 512);
        k_lstm<<<dim3(2, 64), 256>>>(bih, bhh, t);
    }

    // predictions = Hall @ Wout + bout, masked + scattered (tf32 tensor cores)
    mma128<1><<<dim3(250, 10), 256, SM128B>>>(p_Hall, 512, Wout, 32000, bout, out, 512);
}